// round 3
// baseline (speedup 1.0000x reference)
#include <cuda_runtime.h>

// VQ nearest-codebook lookup + straight-through output.
// x:   [32, 64, 64, 64] fp32 (B, C, H, W)  -> rows r = b*4096 + n, n = h*64+w
//      x element (r, c) lives at x[b*262144 + c*4096 + n]  (coalesced across threads)
// emb: [512, 64] fp32
// out: flat [131072, 64] fp32 row-major (reference reshapes flat buffer directly)

#define THREADS    256
#define CHUNK_ROWS 512         // 256 threads * 2 rows
#define GRID       128         // 2 chunks per block -> 256 chunks = 131072 rows
#define KD4        16          // 64 / 4

__global__ void __launch_bounds__(THREADS, 1)
vq_kernel(const float* __restrict__ x, const float* __restrict__ emb,
          float* __restrict__ out)
{
    extern __shared__ float smem[];
    float4* es  = (float4*)smem;          // 512 codes * 16 float4 = 128 KB
    float* e_sq = smem + 512 * 64;        // 512 floats

    const int tid = threadIdx.x;

    // Stage codebook into shared memory (coalesced float4 copy).
    const float4* ev = (const float4*)emb;
    #pragma unroll
    for (int i = tid; i < 512 * KD4; i += THREADS) es[i] = ev[i];
    __syncthreads();

    // Per-code squared norms.
    for (int c = tid; c < 512; c += THREADS) {
        float s = 0.0f;
        #pragma unroll
        for (int kk = 0; kk < KD4; kk++) {
            float4 e = es[c * KD4 + kk];
            s = fmaf(e.x, e.x, s); s = fmaf(e.y, e.y, s);
            s = fmaf(e.z, e.z, s); s = fmaf(e.w, e.w, s);
        }
        e_sq[c] = s;
    }
    __syncthreads();

    float4* outv = (float4*)out;

    #pragma unroll 1
    for (int ci = 0; ci < 2; ci++) {
        const int chunk = blockIdx.x * 2 + ci;
        const int rbase = chunk * CHUNK_ROWS;
        const int r0 = rbase + tid;
        const int r1 = r0 + THREADS;

        // Load both x rows into registers. Channel-strided per thread, but
        // consecutive threads hit consecutive n -> each LDG coalesced.
        float4 x0v[KD4], x1v[KD4];
        {
            const int b0 = r0 >> 12, n0 = r0 & 4095;
            const int b1 = r1 >> 12, n1 = r1 & 4095;
            const float* xp0 = x + (size_t)b0 * 262144 + n0;
            const float* xp1 = x + (size_t)b1 * 262144 + n1;
            #pragma unroll
            for (int kk = 0; kk < KD4; kk++) {
                x0v[kk] = make_float4(xp0[(4*kk+0)*4096], xp0[(4*kk+1)*4096],
                                      xp0[(4*kk+2)*4096], xp0[(4*kk+3)*4096]);
                x1v[kk] = make_float4(xp1[(4*kk+0)*4096], xp1[(4*kk+1)*4096],
                                      xp1[(4*kk+2)*4096], xp1[(4*kk+3)*4096]);
            }
        }

        float best0 = 3.402823466e38f, best1 = 3.402823466e38f;
        int   bi0 = 0, bi1 = 0;

        // Main loop: 4 codes x 2 rows per iteration. 512 FFMA per 64 LDS.128.
        #pragma unroll 1
        for (int c = 0; c < 512; c += 4) {
            float a00 = 0.f, a01 = 0.f, a02 = 0.f, a03 = 0.f;
            float a10 = 0.f, a11 = 0.f, a12 = 0.f, a13 = 0.f;
            #pragma unroll
            for (int kk = 0; kk < KD4; kk++) {
                float4 e0 = es[(c+0) * KD4 + kk];
                float4 e1 = es[(c+1) * KD4 + kk];
                float4 e2 = es[(c+2) * KD4 + kk];
                float4 e3 = es[(c+3) * KD4 + kk];
                float4 p0 = x0v[kk];
                float4 p1 = x1v[kk];
                a00 = fmaf(p0.x, e0.x, a00); a00 = fmaf(p0.y, e0.y, a00);
                a00 = fmaf(p0.z, e0.z, a00); a00 = fmaf(p0.w, e0.w, a00);
                a01 = fmaf(p0.x, e1.x, a01); a01 = fmaf(p0.y, e1.y, a01);
                a01 = fmaf(p0.z, e1.z, a01); a01 = fmaf(p0.w, e1.w, a01);
                a02 = fmaf(p0.x, e2.x, a02); a02 = fmaf(p0.y, e2.y, a02);
                a02 = fmaf(p0.z, e2.z, a02); a02 = fmaf(p0.w, e2.w, a02);
                a03 = fmaf(p0.x, e3.x, a03); a03 = fmaf(p0.y, e3.y, a03);
                a03 = fmaf(p0.z, e3.z, a03); a03 = fmaf(p0.w, e3.w, a03);
                a10 = fmaf(p1.x, e0.x, a10); a10 = fmaf(p1.y, e0.y, a10);
                a10 = fmaf(p1.z, e0.z, a10); a10 = fmaf(p1.w, e0.w, a10);
                a11 = fmaf(p1.x, e1.x, a11); a11 = fmaf(p1.y, e1.y, a11);
                a11 = fmaf(p1.z, e1.z, a11); a11 = fmaf(p1.w, e1.w, a11);
                a12 = fmaf(p1.x, e2.x, a12); a12 = fmaf(p1.y, e2.y, a12);
                a12 = fmaf(p1.z, e2.z, a12); a12 = fmaf(p1.w, e2.w, a12);
                a13 = fmaf(p1.x, e3.x, a13); a13 = fmaf(p1.y, e3.y, a13);
                a13 = fmaf(p1.z, e3.z, a13); a13 = fmaf(p1.w, e3.w, a13);
            }
            // Ascending scan with strict '<' keeps first-index tie-breaking.
            float m;
            m = fmaf(-2.0f, a00, e_sq[c+0]); if (m < best0) { best0 = m; bi0 = c+0; }
            m = fmaf(-2.0f, a01, e_sq[c+1]); if (m < best0) { best0 = m; bi0 = c+1; }
            m = fmaf(-2.0f, a02, e_sq[c+2]); if (m < best0) { best0 = m; bi0 = c+2; }
            m = fmaf(-2.0f, a03, e_sq[c+3]); if (m < best0) { best0 = m; bi0 = c+3; }
            m = fmaf(-2.0f, a10, e_sq[c+0]); if (m < best1) { best1 = m; bi1 = c+0; }
            m = fmaf(-2.0f, a11, e_sq[c+1]); if (m < best1) { best1 = m; bi1 = c+1; }
            m = fmaf(-2.0f, a12, e_sq[c+2]); if (m < best1) { best1 = m; bi1 = c+2; }
            m = fmaf(-2.0f, a13, e_sq[c+3]); if (m < best1) { best1 = m; bi1 = c+3; }
        }

        // Straight-through output: out = x + (q - x), replicated in fp32.
        #pragma unroll
        for (int kk = 0; kk < KD4; kk++) {
            float4 e = es[bi0 * KD4 + kk];
            float4 p = x0v[kk];
            outv[(size_t)r0 * KD4 + kk] =
                make_float4(p.x + (e.x - p.x), p.y + (e.y - p.y),
                            p.z + (e.z - p.z), p.w + (e.w - p.w));
        }
        #pragma unroll
        for (int kk = 0; kk < KD4; kk++) {
            float4 e = es[bi1 * KD4 + kk];
            float4 p = x1v[kk];
            outv[(size_t)r1 * KD4 + kk] =
                make_float4(p.x + (e.x - p.x), p.y + (e.y - p.y),
                            p.z + (e.z - p.z), p.w + (e.w - p.w));
        }
    }
}

extern "C" void kernel_launch(void* const* d_in, const int* in_sizes, int n_in,
                              void* d_out, int out_size)
{
    const float* x   = (const float*)d_in[0];   // 8388608 floats
    const float* emb = (const float*)d_in[1];   // 32768 floats
    float* out = (float*)d_out;                 // 8388608 floats

    const size_t smem = (512 * 64 + 512) * sizeof(float);   // 130.0 KB
    cudaFuncSetAttribute(vq_kernel,
                         cudaFuncAttributeMaxDynamicSharedMemorySize,
                         (int)smem);
    vq_kernel<<<GRID, THREADS, smem>>>(x, emb, out);
}

// round 4
// speedup vs baseline: 1.0550x; 1.0550x over previous
#include <cuda_runtime.h>

// VQ nearest-codebook lookup + straight-through output, fp32x2 packed FFMA.
// x:   [32, 64, 64, 64] fp32 (B, C, H, W)  -> rows r = b*4096 + n
//      x element (r, c) at x[b*262144 + c*4096 + n]  (coalesced across threads)
// emb: [512, 64] fp32
// out: flat [131072, 64] fp32 row-major

#define THREADS    256
#define CHUNK_ROWS 512         // 256 threads * 2 rows
#define GRID       128         // 2 chunks per block
#define KD4        16          // 64 / 4
typedef unsigned long long u64;

// Packed dual fp32 FMA: d.lo += a.lo*b.lo ; d.hi += a.hi*b.hi (IEEE rn each)
__device__ __forceinline__ void ffma2(u64 &d, u64 a, u64 b) {
    asm("fma.rn.f32x2 %0, %1, %2, %0;" : "+l"(d) : "l"(a), "l"(b));
}
__device__ __forceinline__ u64 pack2(float lo, float hi) {
    u64 v; asm("mov.b64 %0, {%1, %2};" : "=l"(v) : "f"(lo), "f"(hi)); return v;
}
__device__ __forceinline__ float hadd2(u64 v) {
    float lo, hi; asm("mov.b64 {%0, %1}, %2;" : "=f"(lo), "=f"(hi) : "l"(v));
    return lo + hi;
}

__global__ void __launch_bounds__(THREADS, 1)
vq_kernel(const float* __restrict__ x, const float* __restrict__ emb,
          float* __restrict__ out)
{
    extern __shared__ float smem[];
    float4*    es   = (float4*)smem;        // 512 codes * 16 float4 = 128 KB
    const u64* es64 = (const u64*)smem;     // same bytes, f32x2 view
    float*     e_sq = smem + 512 * 64;      // 512 floats

    const int tid = threadIdx.x;

    // Stage codebook into shared memory.
    const float4* ev = (const float4*)emb;
    #pragma unroll
    for (int i = tid; i < 512 * KD4; i += THREADS) es[i] = ev[i];
    __syncthreads();

    // Per-code squared norms.
    for (int c = tid; c < 512; c += THREADS) {
        float s = 0.0f;
        #pragma unroll
        for (int kk = 0; kk < KD4; kk++) {
            float4 e = es[c * KD4 + kk];
            s = fmaf(e.x, e.x, s); s = fmaf(e.y, e.y, s);
            s = fmaf(e.z, e.z, s); s = fmaf(e.w, e.w, s);
        }
        e_sq[c] = s;
    }
    __syncthreads();

    float4* outv = (float4*)out;

    #pragma unroll 1
    for (int ci = 0; ci < 2; ci++) {
        const int chunk = blockIdx.x * 2 + ci;
        const int r0 = chunk * CHUNK_ROWS + tid;
        const int r1 = r0 + THREADS;

        // Load both x rows into registers as 32 f32x2 pairs each.
        u64 x0p[32], x1p[32];
        {
            const int b0 = r0 >> 12, n0 = r0 & 4095;
            const int b1 = r1 >> 12, n1 = r1 & 4095;
            const float* xp0 = x + (size_t)b0 * 262144 + n0;
            const float* xp1 = x + (size_t)b1 * 262144 + n1;
            #pragma unroll
            for (int j = 0; j < 32; j++) {
                x0p[j] = pack2(xp0[(2*j)*4096], xp0[(2*j+1)*4096]);
                x1p[j] = pack2(xp1[(2*j)*4096], xp1[(2*j+1)*4096]);
            }
        }

        float best0 = 3.402823466e38f, best1 = 3.402823466e38f;
        int   bi0 = 0, bi1 = 0;

        // 4 codes x 2 rows per iteration: 256 FFMA2 + shared e loads.
        #pragma unroll 1
        for (int c = 0; c < 512; c += 4) {
            const u64* e0 = es64 + (size_t)c * 32;
            const u64* e1 = e0 + 32;
            const u64* e2 = e0 + 64;
            const u64* e3 = e0 + 96;
            u64 a00 = 0, a01 = 0, a02 = 0, a03 = 0;
            u64 a10 = 0, a11 = 0, a12 = 0, a13 = 0;
            #pragma unroll
            for (int j = 0; j < 32; j++) {
                u64 v0 = e0[j], v1 = e1[j], v2 = e2[j], v3 = e3[j];
                u64 p0 = x0p[j], p1 = x1p[j];
                ffma2(a00, p0, v0); ffma2(a01, p0, v1);
                ffma2(a02, p0, v2); ffma2(a03, p0, v3);
                ffma2(a10, p1, v0); ffma2(a11, p1, v1);
                ffma2(a12, p1, v2); ffma2(a13, p1, v3);
            }
            // m = e_sq - 2*cross ; ascending scan, strict '<' keeps first index.
            float m;
            m = fmaf(-2.0f, hadd2(a00), e_sq[c+0]); if (m < best0) { best0 = m; bi0 = c+0; }
            m = fmaf(-2.0f, hadd2(a01), e_sq[c+1]); if (m < best0) { best0 = m; bi0 = c+1; }
            m = fmaf(-2.0f, hadd2(a02), e_sq[c+2]); if (m < best0) { best0 = m; bi0 = c+2; }
            m = fmaf(-2.0f, hadd2(a03), e_sq[c+3]); if (m < best0) { best0 = m; bi0 = c+3; }
            m = fmaf(-2.0f, hadd2(a10), e_sq[c+0]); if (m < best1) { best1 = m; bi1 = c+0; }
            m = fmaf(-2.0f, hadd2(a11), e_sq[c+1]); if (m < best1) { best1 = m; bi1 = c+1; }
            m = fmaf(-2.0f, hadd2(a12), e_sq[c+2]); if (m < best1) { best1 = m; bi1 = c+2; }
            m = fmaf(-2.0f, hadd2(a13), e_sq[c+3]); if (m < best1) { best1 = m; bi1 = c+3; }
        }

        // Straight-through output: out = x + (q - x), replicated in fp32.
        #pragma unroll
        for (int kk = 0; kk < KD4; kk++) {
            float4 e = es[bi0 * KD4 + kk];
            float2 pl, ph;
            asm("mov.b64 {%0, %1}, %2;" : "=f"(pl.x), "=f"(pl.y) : "l"(x0p[2*kk]));
            asm("mov.b64 {%0, %1}, %2;" : "=f"(ph.x), "=f"(ph.y) : "l"(x0p[2*kk+1]));
            outv[(size_t)r0 * KD4 + kk] =
                make_float4(pl.x + (e.x - pl.x), pl.y + (e.y - pl.y),
                            ph.x + (e.z - ph.x), ph.y + (e.w - ph.y));
        }
        #pragma unroll
        for (int kk = 0; kk < KD4; kk++) {
            float4 e = es[bi1 * KD4 + kk];
            float2 pl, ph;
            asm("mov.b64 {%0, %1}, %2;" : "=f"(pl.x), "=f"(pl.y) : "l"(x1p[2*kk]));
            asm("mov.b64 {%0, %1}, %2;" : "=f"(ph.x), "=f"(ph.y) : "l"(x1p[2*kk+1]));
            outv[(size_t)r1 * KD4 + kk] =
                make_float4(pl.x + (e.x - pl.x), pl.y + (e.y - pl.y),
                            ph.x + (e.z - ph.x), ph.y + (e.w - ph.y));
        }
    }
}

extern "C" void kernel_launch(void* const* d_in, const int* in_sizes, int n_in,
                              void* d_out, int out_size)
{
    const float* x   = (const float*)d_in[0];   // 8388608 floats
    const float* emb = (const float*)d_in[1];   // 32768 floats
    float* out = (float*)d_out;                 // 8388608 floats

    const size_t smem = (512 * 64 + 512) * sizeof(float);   // 130 KB
    cudaFuncSetAttribute(vq_kernel,
                         cudaFuncAttributeMaxDynamicSharedMemorySize,
                         (int)smem);
    vq_kernel<<<GRID, THREADS, smem>>>(x, emb, out);
}